// round 11
// baseline (speedup 1.0000x reference)
#include <cuda_runtime.h>
#include <cuda_bf16.h>
#include <math.h>

#define HW 128
#define NPIX (HW*HW)            // 16384
#define NANCH 9
#define NBOX (NPIX*NANCH)       // 147456 = 144*1024
#define IMG_MAX 2048.0f
#define MAX_OUT 300

// ---------------- scratch (static device memory; no allocation) ----------------
__device__ unsigned short g_fs[3][NPIX*1024];    // relu(features) bf16 3-way split
__device__ unsigned short g_as[3][NPIX*512];     // conv1 output bf16 3-way split
__device__ unsigned g_w1s[3][288*4*2048];        // conv1 weights: [tile][n=128][kpair=16]
__device__ unsigned g_w2s[3][144*4*2048];        // conv2 weights
__device__ float g_x2[NPIX*512];                 // conv2 output fp32
__device__ float g_boxes[NBOX*4];
__device__ unsigned g_keys[2][NBOX];
__device__ unsigned g_vals[2][NBOX];
__device__ unsigned g_hist[256*144];
__device__ float g_wt[45*512 + 45];

// ---------------- PTX helpers (compute_103-safe: sm_80 baseline features) ----------------
__device__ __forceinline__ unsigned smem_u32(const void* p) {
    unsigned a;
    asm("{ .reg .u64 t; cvta.to.shared.u64 t, %1; cvt.u32.u64 %0, t; }" : "=r"(a) : "l"(p));
    return a;
}
#define CP16(dst, src) asm volatile("cp.async.cg.shared.global [%0], [%1], 16;" :: "r"(dst), "l"(src) : "memory")
#define CP_COMMIT()    asm volatile("cp.async.commit_group;" ::: "memory")
#define CP_WAIT0()     asm volatile("cp.async.wait_group 0;" ::: "memory")
#define LDSM4(r, addr) asm volatile("ldmatrix.sync.aligned.m8n8.x4.shared.b16 {%0,%1,%2,%3}, [%4];" \
    : "=r"((r)[0]), "=r"((r)[1]), "=r"((r)[2]), "=r"((r)[3]) : "r"(addr))
#define LDSM2(r, addr) asm volatile("ldmatrix.sync.aligned.m8n8.x2.shared.b16 {%0,%1}, [%2];" \
    : "=r"((r)[0]), "=r"((r)[1]) : "r"(addr))
// accumulate variant: D += A*B (tensor-core internal RZ accumulate — keep chains SHORT)
#define MMA16816(dd, aa, bb) \
    asm volatile("mma.sync.aligned.m16n8k16.row.col.f32.bf16.bf16.f32 " \
        "{%0,%1,%2,%3}, {%4,%5,%6,%7}, {%8,%9}, {%0,%1,%2,%3};" \
        : "+f"((dd)[0]), "+f"((dd)[1]), "+f"((dd)[2]), "+f"((dd)[3]) \
        : "r"((aa)[0]), "r"((aa)[1]), "r"((aa)[2]), "r"((aa)[3]), "r"((bb)[0]), "r"((bb)[1]))
// zero-C variant: D = A*B (starts a fresh short chain)
#define MMA16816_Z(dd, aa, bb) \
    asm volatile("mma.sync.aligned.m16n8k16.row.col.f32.bf16.bf16.f32 " \
        "{%0,%1,%2,%3}, {%4,%5,%6,%7}, {%8,%9}, {%10,%11,%12,%13};" \
        : "=f"((dd)[0]), "=f"((dd)[1]), "=f"((dd)[2]), "=f"((dd)[3]) \
        : "r"((aa)[0]), "r"((aa)[1]), "r"((aa)[2]), "r"((aa)[3]), "r"((bb)[0]), "r"((bb)[1]), \
          "f"(0.f), "f"(0.f), "f"(0.f), "f"(0.f))

// ---------------- bf16 3-way exact split ----------------
__device__ __forceinline__ void split3(float v, unsigned short& s0, unsigned short& s1, unsigned short& s2)
{
    __nv_bfloat16 a0 = __float2bfloat16(v);
    float r1 = v - __bfloat162float(a0);
    __nv_bfloat16 a1 = __float2bfloat16(r1);
    float r2 = r1 - __bfloat162float(a1);
    __nv_bfloat16 a2 = __float2bfloat16(r2);
    s0 = __bfloat16_as_ushort(a0);
    s1 = __bfloat16_as_ushort(a1);
    s2 = __bfloat16_as_ushort(a2);
}

// ---------------- feature split: relu + 3-way bf16 ----------------
__global__ void feat_split_kernel(const float* __restrict__ f)
{
    int i = blockIdx.x * 256 + threadIdx.x;     // NPIX*1024 total
    float v = fmaxf(f[i], 0.f);
    unsigned short s0, s1, s2;
    split3(v, s0, s1, s2);
    g_fs[0][i] = s0; g_fs[1][i] = s1; g_fs[2][i] = s2;
}

// ---------------- weight split + transpose into MMA-ready tiles ----------------
template<bool FIRST>
__global__ void wsplit_kernel(const float* __restrict__ w)
{
    __shared__ float ws[32][129];
    const int tile = blockIdx.x;
    const int ch = tile >> 2, nt = tile & 3;
    const int tid = threadIdx.x;                // 256

    for (int i = tid; i < 32*128; i += 256) {
        int kk = i >> 7, nn = i & 127;
        ws[kk][nn] = w[(size_t)(ch*32 + kk)*512 + nt*128 + nn];
    }
    __syncthreads();

    for (int g = tid; g < 2048; g += 256) {
        int nn = g >> 4, kp = g & 15;
        unsigned short a0, a1, a2, b0, b1, b2;
        split3(ws[kp*2][nn],     a0, a1, a2);
        split3(ws[kp*2 + 1][nn], b0, b1, b2);
        size_t o = (size_t)tile*2048 + nn*16 + kp;
        unsigned* d0 = FIRST ? g_w1s[0] : g_w2s[0];
        unsigned* d1 = FIRST ? g_w1s[1] : g_w2s[1];
        unsigned* d2 = FIRST ? g_w1s[2] : g_w2s[2];
        d0[o] = (unsigned)a0 | ((unsigned)b0 << 16);
        d1[o] = (unsigned)a1 | ((unsigned)b1 << 16);
        d2[o] = (unsigned)a2 | ((unsigned)b2 << 16);
    }
}

// ---------------- conv 3x3 as bf16x3 warp-MMA implicit GEMM ----------------
// grid (y=128, nt=4), 512 threads (16 warps, 4x4 grid; warp tile 32m x 32n).
// M=128 pixels, N=128 ch, K chunks of 32. RN-drain every 2 chunks caps RZ chains.
extern __shared__ unsigned char dynsmem[];

template<int CIN, bool FIRST>
__global__ void __launch_bounds__(512, 1) conv_mma_kernel(const float* __restrict__ bias)
{
    constexpr int CPK = CIN/32;
    constexpr int NCH = 9*CPK;                  // even (288 / 144)
    const int y  = blockIdx.x;
    const int nt = blockIdx.y;
    const int n0 = nt << 7;
    const int tid = threadIdx.x;
    const int wid = tid >> 5, lane = tid & 31;
    const int wm = wid >> 2, wn = wid & 3;      // warp grid 4x4: 32m x 32n per warp

    const unsigned sbase = smem_u32(dynsmem);
#define A_OFF(buf, t) ((unsigned)(((buf)*3 + (t))*10240u))
#define B_OFF(buf, t) ((unsigned)(61440u + ((buf)*3 + (t))*10240u))

    float d[2][4][4];       // per-segment tensor-core accumulators (short RZ chains)
    float acc[2][4][4];     // master RN accumulators
#pragma unroll
    for (int mi = 0; mi < 2; mi++)
#pragma unroll
        for (int nj = 0; nj < 4; nj++)
#pragma unroll
            for (int q = 0; q < 4; q++) { d[mi][nj][q] = 0.f; acc[mi][nj][q] = 0.f; }

#define LOAD_CHUNK(CH, BUF) do { \
        int _ch = (CH), _buf = (BUF); \
        int _khw = _ch / CPK; \
        int _kh = _khw / 3, _kw = _khw % 3; \
        int _yy = y + _kh - 1; \
        int _c0 = (_ch % CPK) * 32; \
        for (int g = tid; g < 1536; g += 512) { \
            int t = g >> 9, rem = g & 511; \
            int nn = rem >> 2, gg = rem & 3; \
            const unsigned* bsrc = (FIRST ? g_w1s[t] : g_w2s[t]) \
                + ((size_t)(_ch*4 + nt)*2048 + nn*16 + gg*4); \
            CP16(sbase + B_OFF(_buf, t) + nn*80 + gg*16, bsrc); \
        } \
        if (_yy >= 0 && _yy < HW) { \
            for (int g = tid; g < 1536; g += 512) { \
                int t = g >> 9, rem = g & 511; \
                int row = rem >> 2, gg = rem & 3; \
                int xx = row + _kw - 1; \
                if (xx >= 0 && xx < HW) { \
                    const unsigned short* asrc = (FIRST ? g_fs[t] : g_as[t]) \
                        + ((size_t)(_yy*HW + xx)*CIN + _c0 + gg*8); \
                    CP16(sbase + A_OFF(_buf, t) + row*80 + gg*16, asrc); \
                } else { \
                    *reinterpret_cast<uint4*>(dynsmem + A_OFF(_buf, t) + row*80 + gg*16) \
                        = make_uint4(0,0,0,0); \
                } \
            } \
        } else { \
            for (int g = tid; g < 1536; g += 512) { \
                int t = g >> 9, rem = g & 511; \
                int row = rem >> 2, gg = rem & 3; \
                *reinterpret_cast<uint4*>(dynsmem + A_OFF(_buf, t) + row*80 + gg*16) \
                    = make_uint4(0,0,0,0); \
            } \
        } \
    } while (0)

    LOAD_CHUNK(0, 0);
    CP_COMMIT();

    for (int ch = 0; ch < NCH; ch++) {
        const int buf = ch & 1;
        const bool segstart = ((ch & 1) == 0);   // segment = 2 chunks
        CP_WAIT0();
        __syncthreads();
        if (ch + 1 < NCH) { LOAD_CHUNK(ch+1, buf ^ 1); CP_COMMIT(); }

        // compute this chunk from smem buf
#pragma unroll
        for (int ks = 0; ks < 2; ks++) {
            const unsigned acol = ks*16 + ((lane >> 4) & 1)*8;
            const unsigned arow = wm*32 + (lane & 7) + ((lane >> 3) & 1)*8;
            const unsigned brow = wn*32 + (lane & 7);
            const unsigned bcol = ks*16 + ((lane >> 3) & 1)*8;
#pragma unroll
            for (int ta = 0; ta < 3; ta++) {
                unsigned afr[2][4];
#pragma unroll
                for (int mi = 0; mi < 2; mi++) {
                    unsigned addr = sbase + A_OFF(buf, ta) + (arow + mi*16)*80 + acol*2;
                    LDSM4(afr[mi], addr);
                }
                const int nb = (ta == 0) ? 3 : ((ta == 1) ? 2 : 1);
#pragma unroll
                for (int tb = 0; tb < 3; tb++) {
                    if (tb >= nb) break;
#pragma unroll
                    for (int nj = 0; nj < 4; nj++) {
                        unsigned bfr[2];
                        unsigned baddr = sbase + B_OFF(buf, tb) + (brow + nj*8)*80 + bcol*2;
                        LDSM2(bfr, baddr);
                        if (ks == 0 && ta == 0 && tb == 0 && segstart) {
#pragma unroll
                            for (int mi = 0; mi < 2; mi++)
                                MMA16816_Z(d[mi][nj], afr[mi], bfr);
                        } else {
#pragma unroll
                            for (int mi = 0; mi < 2; mi++)
                                MMA16816(d[mi][nj], afr[mi], bfr);
                        }
                    }
                }
            }
        }
        if (ch & 1) {   // segment end: RN drain into master accumulators
#pragma unroll
            for (int mi = 0; mi < 2; mi++)
#pragma unroll
                for (int nj = 0; nj < 4; nj++)
#pragma unroll
                    for (int q = 0; q < 4; q++) acc[mi][nj][q] += d[mi][nj][q];
        }
        __syncthreads();
    }

    // epilogue
    const int gid = lane >> 2, tg = lane & 3;
#pragma unroll
    for (int mi = 0; mi < 2; mi++) {
#pragma unroll
        for (int half = 0; half < 2; half++) {
            const int px = y*HW + wm*32 + mi*16 + gid + half*8;
#pragma unroll
            for (int nj = 0; nj < 4; nj++) {
                const int n = n0 + wn*32 + nj*8 + tg*2;
                float v0 = acc[mi][nj][half*2 + 0] + __ldg(&bias[n]);
                float v1 = acc[mi][nj][half*2 + 1] + __ldg(&bias[n+1]);
                if (FIRST) {
                    v0 = fmaxf(v0, 0.f);
                    v1 = fmaxf(v1, 0.f);
                    unsigned short a0,a1,a2,b0,b1,b2;
                    split3(v0, a0, a1, a2);
                    split3(v1, b0, b1, b2);
                    size_t e = (size_t)px*512 + n;
                    *reinterpret_cast<unsigned*>(&g_as[0][e]) = (unsigned)a0 | ((unsigned)b0 << 16);
                    *reinterpret_cast<unsigned*>(&g_as[1][e]) = (unsigned)a1 | ((unsigned)b1 << 16);
                    *reinterpret_cast<unsigned*>(&g_as[2][e]) = (unsigned)a2 | ((unsigned)b2 << 16);
                } else {
                    *reinterpret_cast<float2*>(&g_x2[(size_t)px*512 + n]) = make_float2(v0, v1);
                }
            }
        }
    }
#undef LOAD_CHUNK
#undef A_OFF
#undef B_OFF
}

// ---------------- head weight transpose ----------------
__global__ void prep_wt_kernel(const float* __restrict__ wsc, const float* __restrict__ bsc,
                               const float* __restrict__ wbx, const float* __restrict__ bbx)
{
    int t = blockIdx.x * blockDim.x + threadIdx.x;
    if (t < 45*512) {
        int o = t / 512, c = t % 512;
        g_wt[t] = (o < 9) ? wsc[c*9 + o] : wbx[c*36 + (o-9)];
    }
    if (t < 45) g_wt[45*512 + t] = (t < 9) ? bsc[t] : bbx[t-9];
}

// ---------------- heads (1x1 conv) + sigmoid + decode + keygen ----------------
__global__ void heads_kernel()
{
    float* ws  = reinterpret_cast<float*>(dynsmem);  // 45*512
    float* xsm = ws + 45*512;                        // 16*512
    float* ho  = xsm + 16*512;                       // 16*45

    const int tid  = threadIdx.x;
    const int lane = tid & 31;
    const int wrp  = tid >> 5;
    const int p0   = blockIdx.x * 16;

    for (int i = tid; i < 45*512; i += 256) ws[i] = g_wt[i];
    for (int i = tid; i < 16*512; i += 256) xsm[i] = g_x2[(size_t)p0*512 + i];
    __syncthreads();

#pragma unroll
    for (int pi = 0; pi < 2; pi++) {
        const int px = wrp*2 + pi;
        float xr[16];
#pragma unroll
        for (int i = 0; i < 16; i++) xr[i] = xsm[px*512 + lane + 32*i];
        for (int o = 0; o < 45; o++) {
            const float* wr = ws + o*512;
            float acc = 0.f;
#pragma unroll
            for (int i = 0; i < 16; i++) acc = fmaf(xr[i], wr[lane + 32*i], acc);
#pragma unroll
            for (int off = 16; off > 0; off >>= 1)
                acc += __shfl_xor_sync(0xFFFFFFFFu, acc, off);
            if (lane == 0) ho[px*45 + o] = acc + g_wt[45*512 + o];
        }
    }
    __syncthreads();

    if (tid < 144) {
        int pp = tid / 9, a = tid % 9;
        int pg = p0 + pp;
        const float* h5 = ho + pp*45;
        float logit = h5[a];
        float sc = 1.f / (1.f + expf(-logit));
        float dy = h5[9 + 4*a + 0];
        float dx = h5[9 + 4*a + 1];
        float dh = h5[9 + 4*a + 2];
        float dw = h5[9 + 4*a + 3];
        int yy = pg >> 7, xx = pg & 127;
        float scale = (a < 3) ? 128.f : ((a < 6) ? 256.f : 512.f);
        int rm = a % 3;
        float ratio = (rm == 0) ? 0.5f : ((rm == 1) ? 1.f : 2.f);
        float sr = sqrtf(ratio);
        float ah = scale * sr, aw = scale / sr;
        float acy = (yy + 0.5f) * 16.f, acx = (xx + 0.5f) * 16.f;
        float cy = acy + dy * ah, cx = acx + dx * aw;
        float h = ah * expf(dh), w = aw * expf(dw);
        float y1 = fminf(fmaxf(cy - 0.5f*h, 0.f), IMG_MAX);
        float x1 = fminf(fmaxf(cx - 0.5f*w, 0.f), IMG_MAX);
        float y2 = fminf(fmaxf(cy + 0.5f*h, 0.f), IMG_MAX);
        float x2 = fminf(fmaxf(cx + 0.5f*w, 0.f), IMG_MAX);
        int idx = pg*9 + a;
        *reinterpret_cast<float4*>(&g_boxes[idx*4]) = make_float4(y1, x1, y2, x2);
        g_keys[0][idx] = ~__float_as_uint(sc);
        g_vals[0][idx] = (unsigned)idx;
    }
}

// ---------------- stable LSD radix sort (4 x 8-bit passes) ----------------
__global__ void radix_hist_kernel(int src, int shift)
{
    __shared__ int h[256];
    const int tid = threadIdx.x;
    h[tid] = 0;
    __syncthreads();
    const int base = blockIdx.x * 1024;
#pragma unroll
    for (int j = 0; j < 4; j++) {
        unsigned k = g_keys[src][base + j*256 + tid];
        atomicAdd(&h[(k >> shift) & 255], 1);
    }
    __syncthreads();
    g_hist[tid*144 + blockIdx.x] = (unsigned)h[tid];
}

__global__ void radix_scan_kernel()
{
    __shared__ unsigned s[1024];
    const int t = threadIdx.x;
    const int base = t * 36;
    unsigned loc[36];
    unsigned sum = 0;
#pragma unroll
    for (int i = 0; i < 36; i++) { loc[i] = g_hist[base + i]; sum += loc[i]; }
    s[t] = sum;
    __syncthreads();
    for (int off = 1; off < 1024; off <<= 1) {
        unsigned v = (t >= off) ? s[t - off] : 0u;
        __syncthreads();
        s[t] += v;
        __syncthreads();
    }
    unsigned run = s[t] - sum;
#pragma unroll
    for (int i = 0; i < 36; i++) { unsigned tmp = loc[i]; g_hist[base + i] = run; run += tmp; }
}

__global__ void radix_scatter_kernel(int src, int dst, int shift)
{
    __shared__ unsigned skey[1024];
    __shared__ unsigned sval[1024];
    __shared__ unsigned char sdig[1024];
    __shared__ unsigned short lrank[1024];
    const int tid = threadIdx.x;
    const int base = blockIdx.x * 1024;
#pragma unroll
    for (int j = 0; j < 4; j++) {
        int i = j*256 + tid;
        unsigned k = g_keys[src][base + i];
        skey[i] = k;
        sval[i] = g_vals[src][base + i];
        sdig[i] = (unsigned char)((k >> shift) & 255);
    }
    __syncthreads();
    {
        unsigned char dg = (unsigned char)tid;
        unsigned short cnt = 0;
        for (int i = 0; i < 1024; i++) {
            if (sdig[i] == dg) lrank[i] = cnt++;
        }
    }
    __syncthreads();
#pragma unroll
    for (int j = 0; j < 4; j++) {
        int i = j*256 + tid;
        unsigned pos = g_hist[(unsigned)sdig[i]*144 + blockIdx.x] + lrank[i];
        g_keys[dst][pos] = skey[i];
        g_vals[dst][pos] = sval[i];
    }
}

// ---------------- greedy NMS over sorted candidates ----------------
__global__ void nms_kernel(float* __restrict__ out, int out_size)
{
    __shared__ float sy1[MAX_OUT], sx1[MAX_OUT], sy2[MAX_OUT], sx2[MAX_OUT], sar[MAX_OUT];
    __shared__ int nsel;
    __shared__ int st;
    __shared__ float cand[5];
    const int tid = threadIdx.x;

    for (int i = tid; i < out_size; i += blockDim.x) out[i] = 0.f;
    if (tid == 0) nsel = 0;
    __syncthreads();

    for (int i = 0; i < NBOX; i++) {
        if (tid == 0) {
            unsigned k = g_keys[0][i];
            float sc = __uint_as_float(~k);
            if (!(sc >= 0.5f)) {
                st = 2;
            } else {
                st = 0;
                unsigned id = g_vals[0][i];
                float4 b = *reinterpret_cast<const float4*>(&g_boxes[id*4]);
                cand[0] = b.x; cand[1] = b.y; cand[2] = b.z; cand[3] = b.w;
                cand[4] = sc;
            }
        }
        __syncthreads();
        if (st == 2) break;

        float y1 = cand[0], x1 = cand[1], y2 = cand[2], x2 = cand[3];
        float ca = (y2 - y1) * (x2 - x1);
        int m = nsel;
        for (int s = tid; s < m; s += blockDim.x) {
            float iy = fmaxf(0.f, fminf(y2, sy2[s]) - fmaxf(y1, sy1[s]));
            float ix = fmaxf(0.f, fminf(x2, sx2[s]) - fmaxf(x1, sx1[s]));
            float inter = iy * ix;
            float iou = inter / (sar[s] + ca - inter + 1e-9f);
            if (iou > 0.7f) st = 1;
        }
        __syncthreads();
        if (st == 0 && tid == 0) {
            sy1[m] = y1; sx1[m] = x1; sy2[m] = y2; sx2[m] = x2; sar[m] = ca;
            if (m*4 + 3 < out_size) {
                out[m*4 + 0] = y1; out[m*4 + 1] = x1; out[m*4 + 2] = y2; out[m*4 + 3] = x2;
            }
            if (1200 + m < out_size) out[1200 + m] = cand[4];
            if (1500 + m < out_size) out[1500 + m] = 1.f;
            nsel = m + 1;
        }
        __syncthreads();
        if (nsel >= MAX_OUT) break;
    }
}

// ---------------- launch ----------------
extern "C" void kernel_launch(void* const* d_in, const int* in_sizes, int n_in,
                              void* d_out, int out_size)
{
    const float *features = 0, *w1 = 0, *b1 = 0, *w2 = 0, *b2 = 0;
    const float *wsc = 0, *bsc = 0, *wbx = 0, *bbx = 0;
    for (int i = 0; i < n_in; i++) {
        int sz = in_sizes[i];
        const float* p = (const float*)d_in[i];
        switch (sz) {
            case 16777216: features = p; break;
            case 4718592:  w1 = p; break;
            case 2359296:  w2 = p; break;
            case 18432:    wbx = p; break;
            case 4608:     wsc = p; break;
            case 36:       bbx = p; break;
            case 9:        bsc = p; break;
            case 512:      if (!b1) b1 = p; else b2 = p; break;
            default: break;
        }
    }
    if (!b2) b2 = b1;
    float* out = (float*)d_out;

    feat_split_kernel<<<NPIX*1024/256, 256>>>(features);
    wsplit_kernel<true ><<<288*4, 256>>>(w1);
    wsplit_kernel<false><<<144*4, 256>>>(w2);

    const int conv_smem = 122880;    // (A + B) x 3 splits x 2 buffers x 10240B
    cudaFuncSetAttribute(conv_mma_kernel<1024, true >, cudaFuncAttributeMaxDynamicSharedMemorySize, conv_smem);
    cudaFuncSetAttribute(conv_mma_kernel< 512, false>, cudaFuncAttributeMaxDynamicSharedMemorySize, conv_smem);
    conv_mma_kernel<1024, true ><<<dim3(HW, 4), 512, conv_smem>>>(b1);
    conv_mma_kernel< 512, false><<<dim3(HW, 4), 512, conv_smem>>>(b2);

    prep_wt_kernel<<<91, 256>>>(wsc, bsc, wbx, bbx);

    const int heads_smem = (45*512 + 16*512 + 16*45) * (int)sizeof(float);
    cudaFuncSetAttribute(heads_kernel, cudaFuncAttributeMaxDynamicSharedMemorySize, heads_smem);
    heads_kernel<<<NPIX/16, 256, heads_smem>>>();

    int src = 0;
    for (int pass = 0; pass < 4; pass++) {
        int shift = pass * 8;
        int dst = src ^ 1;
        radix_hist_kernel<<<144, 256>>>(src, shift);
        radix_scan_kernel<<<1, 1024>>>();
        radix_scatter_kernel<<<144, 256>>>(src, dst, shift);
        src = dst;
    }

    nms_kernel<<<1, 256>>>(out, out_size);
}

// round 12
// speedup vs baseline: 1.0525x; 1.0525x over previous
#include <cuda_runtime.h>
#include <cuda_bf16.h>
#include <math.h>

#define HW 128
#define NPIX (HW*HW)            // 16384
#define NANCH 9
#define NBOX (NPIX*NANCH)       // 147456 = 144*1024
#define IMG_MAX 2048.0f
#define MAX_OUT 300

// ---------------- scratch (static device memory; no allocation) ----------------
__device__ unsigned short g_fs[3][NPIX*1024];    // relu(features) bf16 3-way split
__device__ unsigned short g_as[3][NPIX*512];     // conv1 output bf16 3-way split
__device__ unsigned g_w1s[3][288*4*2048];        // conv1 weights: [tile][n=128][kpair=16]
__device__ unsigned g_w2s[3][144*4*2048];        // conv2 weights
__device__ float g_x2[NPIX*512];                 // conv2 output fp32
__device__ float g_boxes[NBOX*4];
__device__ unsigned g_keys[2][NBOX];
__device__ unsigned g_vals[2][NBOX];
__device__ unsigned g_hist[256*144];
__device__ float g_wt[45*512 + 45];

// ---------------- PTX helpers (compute_103-safe: sm_80 baseline features) ----------------
__device__ __forceinline__ unsigned smem_u32(const void* p) {
    unsigned a;
    asm("{ .reg .u64 t; cvta.to.shared.u64 t, %1; cvt.u32.u64 %0, t; }" : "=r"(a) : "l"(p));
    return a;
}
#define CP16(dst, src) asm volatile("cp.async.cg.shared.global [%0], [%1], 16;" :: "r"(dst), "l"(src) : "memory")
#define CP_COMMIT()    asm volatile("cp.async.commit_group;" ::: "memory")
#define CP_WAIT1()     asm volatile("cp.async.wait_group 1;" ::: "memory")
#define LDSM4(r, addr) asm volatile("ldmatrix.sync.aligned.m8n8.x4.shared.b16 {%0,%1,%2,%3}, [%4];" \
    : "=r"((r)[0]), "=r"((r)[1]), "=r"((r)[2]), "=r"((r)[3]) : "r"(addr))
#define LDSM2(r, addr) asm volatile("ldmatrix.sync.aligned.m8n8.x2.shared.b16 {%0,%1}, [%2];" \
    : "=r"((r)[0]), "=r"((r)[1]) : "r"(addr))
// accumulate variant: D += A*B (tensor-core internal RZ accumulate — keep chains SHORT)
#define MMA16816(dd, aa, bb) \
    asm volatile("mma.sync.aligned.m16n8k16.row.col.f32.bf16.bf16.f32 " \
        "{%0,%1,%2,%3}, {%4,%5,%6,%7}, {%8,%9}, {%0,%1,%2,%3};" \
        : "+f"((dd)[0]), "+f"((dd)[1]), "+f"((dd)[2]), "+f"((dd)[3]) \
        : "r"((aa)[0]), "r"((aa)[1]), "r"((aa)[2]), "r"((aa)[3]), "r"((bb)[0]), "r"((bb)[1]))
// zero-C variant: D = A*B (starts a fresh short chain)
#define MMA16816_Z(dd, aa, bb) \
    asm volatile("mma.sync.aligned.m16n8k16.row.col.f32.bf16.bf16.f32 " \
        "{%0,%1,%2,%3}, {%4,%5,%6,%7}, {%8,%9}, {%10,%11,%12,%13};" \
        : "=f"((dd)[0]), "=f"((dd)[1]), "=f"((dd)[2]), "=f"((dd)[3]) \
        : "r"((aa)[0]), "r"((aa)[1]), "r"((aa)[2]), "r"((aa)[3]), "r"((bb)[0]), "r"((bb)[1]), \
          "f"(0.f), "f"(0.f), "f"(0.f), "f"(0.f))

// ---------------- bf16 3-way exact split ----------------
__device__ __forceinline__ void split3(float v, unsigned short& s0, unsigned short& s1, unsigned short& s2)
{
    __nv_bfloat16 a0 = __float2bfloat16(v);
    float r1 = v - __bfloat162float(a0);
    __nv_bfloat16 a1 = __float2bfloat16(r1);
    float r2 = r1 - __bfloat162float(a1);
    __nv_bfloat16 a2 = __float2bfloat16(r2);
    s0 = __bfloat16_as_ushort(a0);
    s1 = __bfloat16_as_ushort(a1);
    s2 = __bfloat16_as_ushort(a2);
}

// ---------------- feature split: relu + 3-way bf16 ----------------
__global__ void feat_split_kernel(const float* __restrict__ f)
{
    int i = blockIdx.x * 256 + threadIdx.x;     // NPIX*1024 total
    float v = fmaxf(f[i], 0.f);
    unsigned short s0, s1, s2;
    split3(v, s0, s1, s2);
    g_fs[0][i] = s0; g_fs[1][i] = s1; g_fs[2][i] = s2;
}

// ---------------- weight split + transpose into MMA-ready tiles ----------------
template<bool FIRST>
__global__ void wsplit_kernel(const float* __restrict__ w)
{
    __shared__ float ws[32][129];
    const int tile = blockIdx.x;
    const int ch = tile >> 2, nt = tile & 3;
    const int tid = threadIdx.x;                // 256

    for (int i = tid; i < 32*128; i += 256) {
        int kk = i >> 7, nn = i & 127;
        ws[kk][nn] = w[(size_t)(ch*32 + kk)*512 + nt*128 + nn];
    }
    __syncthreads();

    for (int g = tid; g < 2048; g += 256) {
        int nn = g >> 4, kp = g & 15;
        unsigned short a0, a1, a2, b0, b1, b2;
        split3(ws[kp*2][nn],     a0, a1, a2);
        split3(ws[kp*2 + 1][nn], b0, b1, b2);
        size_t o = (size_t)tile*2048 + nn*16 + kp;
        unsigned* d0 = FIRST ? g_w1s[0] : g_w2s[0];
        unsigned* d1 = FIRST ? g_w1s[1] : g_w2s[1];
        unsigned* d2 = FIRST ? g_w1s[2] : g_w2s[2];
        d0[o] = (unsigned)a0 | ((unsigned)b0 << 16);
        d1[o] = (unsigned)a1 | ((unsigned)b1 << 16);
        d2[o] = (unsigned)a2 | ((unsigned)b2 << 16);
    }
}

// ---------------- conv 3x3 as bf16x3 warp-MMA implicit GEMM ----------------
// grid (y=128, nt=4), 256 threads (8 warps, 2x4 grid; warp tile 64m x 32n).
// Triple-buffered smem, prefetch distance 2, ONE barrier per chunk.
// B fragments hoisted per ks (read once, reused across the 3 A splits).
// RN-drain every 2 chunks caps tensor-core RZ accumulation chains.
extern __shared__ unsigned char dynsmem[];

template<int CIN, bool FIRST>
__global__ void __launch_bounds__(256, 1) conv_mma_kernel(const float* __restrict__ bias)
{
    constexpr int CPK = CIN/32;
    constexpr int NCH = 9*CPK;                  // even (288 / 144)
    const int y  = blockIdx.x;
    const int nt = blockIdx.y;
    const int n0 = nt << 7;
    const int tid = threadIdx.x;
    const int wid = tid >> 5, lane = tid & 31;
    const int wm = wid >> 2, wn = wid & 3;      // warp grid 2x4: 64m x 32n per warp

    const unsigned sbase = smem_u32(dynsmem);
    // buffer b (0..2): A at b*61440, B at b*61440 + 30720; each split t is 10240B
#define A_OFF(buf, t) ((unsigned)((buf)*61440u + (t)*10240u))
#define B_OFF(buf, t) ((unsigned)((buf)*61440u + 30720u + (t)*10240u))

    float d[4][4][4];       // per-segment tensor-core accumulators (short RZ chains)
    float acc[4][4][4];     // master RN accumulators
#pragma unroll
    for (int mi = 0; mi < 4; mi++)
#pragma unroll
        for (int nj = 0; nj < 4; nj++)
#pragma unroll
            for (int q = 0; q < 4; q++) { d[mi][nj][q] = 0.f; acc[mi][nj][q] = 0.f; }

#define LOAD_CHUNK(CH, BUF) do { \
        int _ch = (CH), _buf = (BUF); \
        int _khw = _ch / CPK; \
        int _kh = _khw / 3, _kw = _khw % 3; \
        int _yy = y + _kh - 1; \
        int _c0 = (_ch % CPK) * 32; \
        for (int g = tid; g < 1536; g += 256) { \
            int t = g >> 9, rem = g & 511; \
            int nn = rem >> 2, gg = rem & 3; \
            const unsigned* bsrc = (FIRST ? g_w1s[t] : g_w2s[t]) \
                + ((size_t)(_ch*4 + nt)*2048 + nn*16 + gg*4); \
            CP16(sbase + B_OFF(_buf, t) + nn*80 + gg*16, bsrc); \
        } \
        if (_yy >= 0 && _yy < HW) { \
            for (int g = tid; g < 1536; g += 256) { \
                int t = g >> 9, rem = g & 511; \
                int row = rem >> 2, gg = rem & 3; \
                int xx = row + _kw - 1; \
                if (xx >= 0 && xx < HW) { \
                    const unsigned short* asrc = (FIRST ? g_fs[t] : g_as[t]) \
                        + ((size_t)(_yy*HW + xx)*CIN + _c0 + gg*8); \
                    CP16(sbase + A_OFF(_buf, t) + row*80 + gg*16, asrc); \
                } else { \
                    *reinterpret_cast<uint4*>(dynsmem + A_OFF(_buf, t) + row*80 + gg*16) \
                        = make_uint4(0,0,0,0); \
                } \
            } \
        } else { \
            for (int g = tid; g < 1536; g += 256) { \
                int t = g >> 9, rem = g & 511; \
                int row = rem >> 2, gg = rem & 3; \
                *reinterpret_cast<uint4*>(dynsmem + A_OFF(_buf, t) + row*80 + gg*16) \
                    = make_uint4(0,0,0,0); \
            } \
        } \
    } while (0)

    LOAD_CHUNK(0, 0);
    CP_COMMIT();
    if (NCH > 1) { LOAD_CHUNK(1, 1); CP_COMMIT(); }

    for (int ch = 0; ch < NCH; ch++) {
        const int buf = ch % 3;
        const bool segstart = ((ch & 1) == 0);   // segment = 2 chunks
        CP_WAIT1();              // group for chunk `ch` complete; ch+1 may fly
        __syncthreads();         // single barrier per chunk
        if (ch + 2 < NCH) { LOAD_CHUNK(ch+2, (ch+2) % 3); CP_COMMIT(); }

        // compute this chunk from smem buf
#pragma unroll
        for (int ks = 0; ks < 2; ks++) {
            const unsigned acol = ks*16 + ((lane >> 4) & 1)*8;
            const unsigned arow = wm*64 + (lane & 7) + ((lane >> 3) & 1)*8;
            const unsigned brow = wn*32 + (lane & 7);
            const unsigned bcol = ks*16 + ((lane >> 3) & 1)*8;

            // hoist ALL B fragments for this ks (reused across the 3 A splits)
            unsigned bfr[3][4][2];
#pragma unroll
            for (int tb = 0; tb < 3; tb++)
#pragma unroll
                for (int nj = 0; nj < 4; nj++) {
                    unsigned baddr = sbase + B_OFF(buf, tb) + (brow + nj*8)*80 + bcol*2;
                    LDSM2(bfr[tb][nj], baddr);
                }

#pragma unroll
            for (int ta = 0; ta < 3; ta++) {
                unsigned afr[4][4];
#pragma unroll
                for (int mi = 0; mi < 4; mi++) {
                    unsigned addr = sbase + A_OFF(buf, ta) + (arow + mi*16)*80 + acol*2;
                    LDSM4(afr[mi], addr);
                }
                const int nb = (ta == 0) ? 3 : ((ta == 1) ? 2 : 1);
#pragma unroll
                for (int tb = 0; tb < 3; tb++) {
                    if (tb >= nb) break;
#pragma unroll
                    for (int nj = 0; nj < 4; nj++) {
                        if (ks == 0 && ta == 0 && tb == 0 && segstart) {
#pragma unroll
                            for (int mi = 0; mi < 4; mi++)
                                MMA16816_Z(d[mi][nj], afr[mi], bfr[tb][nj]);
                        } else {
#pragma unroll
                            for (int mi = 0; mi < 4; mi++)
                                MMA16816(d[mi][nj], afr[mi], bfr[tb][nj]);
                        }
                    }
                }
            }
        }
        if (ch & 1) {   // segment end: RN drain into master accumulators
#pragma unroll
            for (int mi = 0; mi < 4; mi++)
#pragma unroll
                for (int nj = 0; nj < 4; nj++)
#pragma unroll
                    for (int q = 0; q < 4; q++) acc[mi][nj][q] += d[mi][nj][q];
        }
        // no trailing barrier: writes go to buffer (ch+2)%3, last read at ch-1
    }

    // epilogue
    const int gid = lane >> 2, tg = lane & 3;
#pragma unroll
    for (int mi = 0; mi < 4; mi++) {
#pragma unroll
        for (int half = 0; half < 2; half++) {
            const int px = y*HW + wm*64 + mi*16 + gid + half*8;
#pragma unroll
            for (int nj = 0; nj < 4; nj++) {
                const int n = n0 + wn*32 + nj*8 + tg*2;
                float v0 = acc[mi][nj][half*2 + 0] + __ldg(&bias[n]);
                float v1 = acc[mi][nj][half*2 + 1] + __ldg(&bias[n+1]);
                if (FIRST) {
                    v0 = fmaxf(v0, 0.f);
                    v1 = fmaxf(v1, 0.f);
                    unsigned short a0,a1,a2,b0,b1,b2;
                    split3(v0, a0, a1, a2);
                    split3(v1, b0, b1, b2);
                    size_t e = (size_t)px*512 + n;
                    *reinterpret_cast<unsigned*>(&g_as[0][e]) = (unsigned)a0 | ((unsigned)b0 << 16);
                    *reinterpret_cast<unsigned*>(&g_as[1][e]) = (unsigned)a1 | ((unsigned)b1 << 16);
                    *reinterpret_cast<unsigned*>(&g_as[2][e]) = (unsigned)a2 | ((unsigned)b2 << 16);
                } else {
                    *reinterpret_cast<float2*>(&g_x2[(size_t)px*512 + n]) = make_float2(v0, v1);
                }
            }
        }
    }
#undef LOAD_CHUNK
#undef A_OFF
#undef B_OFF
}

// ---------------- head weight transpose ----------------
__global__ void prep_wt_kernel(const float* __restrict__ wsc, const float* __restrict__ bsc,
                               const float* __restrict__ wbx, const float* __restrict__ bbx)
{
    int t = blockIdx.x * blockDim.x + threadIdx.x;
    if (t < 45*512) {
        int o = t / 512, c = t % 512;
        g_wt[t] = (o < 9) ? wsc[c*9 + o] : wbx[c*36 + (o-9)];
    }
    if (t < 45) g_wt[45*512 + t] = (t < 9) ? bsc[t] : bbx[t-9];
}

// ---------------- heads (1x1 conv) + sigmoid + decode + keygen ----------------
__global__ void heads_kernel()
{
    float* ws  = reinterpret_cast<float*>(dynsmem);  // 45*512
    float* xsm = ws + 45*512;                        // 16*512
    float* ho  = xsm + 16*512;                       // 16*45

    const int tid  = threadIdx.x;
    const int lane = tid & 31;
    const int wrp  = tid >> 5;
    const int p0   = blockIdx.x * 16;

    for (int i = tid; i < 45*512; i += 256) ws[i] = g_wt[i];
    for (int i = tid; i < 16*512; i += 256) xsm[i] = g_x2[(size_t)p0*512 + i];
    __syncthreads();

#pragma unroll
    for (int pi = 0; pi < 2; pi++) {
        const int px = wrp*2 + pi;
        float xr[16];
#pragma unroll
        for (int i = 0; i < 16; i++) xr[i] = xsm[px*512 + lane + 32*i];
        for (int o = 0; o < 45; o++) {
            const float* wr = ws + o*512;
            float acc = 0.f;
#pragma unroll
            for (int i = 0; i < 16; i++) acc = fmaf(xr[i], wr[lane + 32*i], acc);
#pragma unroll
            for (int off = 16; off > 0; off >>= 1)
                acc += __shfl_xor_sync(0xFFFFFFFFu, acc, off);
            if (lane == 0) ho[px*45 + o] = acc + g_wt[45*512 + o];
        }
    }
    __syncthreads();

    if (tid < 144) {
        int pp = tid / 9, a = tid % 9;
        int pg = p0 + pp;
        const float* h5 = ho + pp*45;
        float logit = h5[a];
        float sc = 1.f / (1.f + expf(-logit));
        float dy = h5[9 + 4*a + 0];
        float dx = h5[9 + 4*a + 1];
        float dh = h5[9 + 4*a + 2];
        float dw = h5[9 + 4*a + 3];
        int yy = pg >> 7, xx = pg & 127;
        float scale = (a < 3) ? 128.f : ((a < 6) ? 256.f : 512.f);
        int rm = a % 3;
        float ratio = (rm == 0) ? 0.5f : ((rm == 1) ? 1.f : 2.f);
        float sr = sqrtf(ratio);
        float ah = scale * sr, aw = scale / sr;
        float acy = (yy + 0.5f) * 16.f, acx = (xx + 0.5f) * 16.f;
        float cy = acy + dy * ah, cx = acx + dx * aw;
        float h = ah * expf(dh), w = aw * expf(dw);
        float y1 = fminf(fmaxf(cy - 0.5f*h, 0.f), IMG_MAX);
        float x1 = fminf(fmaxf(cx - 0.5f*w, 0.f), IMG_MAX);
        float y2 = fminf(fmaxf(cy + 0.5f*h, 0.f), IMG_MAX);
        float x2 = fminf(fmaxf(cx + 0.5f*w, 0.f), IMG_MAX);
        int idx = pg*9 + a;
        *reinterpret_cast<float4*>(&g_boxes[idx*4]) = make_float4(y1, x1, y2, x2);
        g_keys[0][idx] = ~__float_as_uint(sc);
        g_vals[0][idx] = (unsigned)idx;
    }
}

// ---------------- stable LSD radix sort (4 x 8-bit passes) ----------------
__global__ void radix_hist_kernel(int src, int shift)
{
    __shared__ int h[256];
    const int tid = threadIdx.x;
    h[tid] = 0;
    __syncthreads();
    const int base = blockIdx.x * 1024;
#pragma unroll
    for (int j = 0; j < 4; j++) {
        unsigned k = g_keys[src][base + j*256 + tid];
        atomicAdd(&h[(k >> shift) & 255], 1);
    }
    __syncthreads();
    g_hist[tid*144 + blockIdx.x] = (unsigned)h[tid];
}

__global__ void radix_scan_kernel()
{
    __shared__ unsigned s[1024];
    const int t = threadIdx.x;
    const int base = t * 36;
    unsigned loc[36];
    unsigned sum = 0;
#pragma unroll
    for (int i = 0; i < 36; i++) { loc[i] = g_hist[base + i]; sum += loc[i]; }
    s[t] = sum;
    __syncthreads();
    for (int off = 1; off < 1024; off <<= 1) {
        unsigned v = (t >= off) ? s[t - off] : 0u;
        __syncthreads();
        s[t] += v;
        __syncthreads();
    }
    unsigned run = s[t] - sum;
#pragma unroll
    for (int i = 0; i < 36; i++) { unsigned tmp = loc[i]; g_hist[base + i] = run; run += tmp; }
}

__global__ void radix_scatter_kernel(int src, int dst, int shift)
{
    __shared__ unsigned skey[1024];
    __shared__ unsigned sval[1024];
    __shared__ unsigned char sdig[1024];
    __shared__ unsigned short lrank[1024];
    const int tid = threadIdx.x;
    const int base = blockIdx.x * 1024;
#pragma unroll
    for (int j = 0; j < 4; j++) {
        int i = j*256 + tid;
        unsigned k = g_keys[src][base + i];
        skey[i] = k;
        sval[i] = g_vals[src][base + i];
        sdig[i] = (unsigned char)((k >> shift) & 255);
    }
    __syncthreads();
    {
        unsigned char dg = (unsigned char)tid;
        unsigned short cnt = 0;
        for (int i = 0; i < 1024; i++) {
            if (sdig[i] == dg) lrank[i] = cnt++;
        }
    }
    __syncthreads();
#pragma unroll
    for (int j = 0; j < 4; j++) {
        int i = j*256 + tid;
        unsigned pos = g_hist[(unsigned)sdig[i]*144 + blockIdx.x] + lrank[i];
        g_keys[dst][pos] = skey[i];
        g_vals[dst][pos] = sval[i];
    }
}

// ---------------- greedy NMS over sorted candidates ----------------
__global__ void nms_kernel(float* __restrict__ out, int out_size)
{
    __shared__ float sy1[MAX_OUT], sx1[MAX_OUT], sy2[MAX_OUT], sx2[MAX_OUT], sar[MAX_OUT];
    __shared__ int nsel;
    __shared__ int st;
    __shared__ float cand[5];
    const int tid = threadIdx.x;

    for (int i = tid; i < out_size; i += blockDim.x) out[i] = 0.f;
    if (tid == 0) nsel = 0;
    __syncthreads();

    for (int i = 0; i < NBOX; i++) {
        if (tid == 0) {
            unsigned k = g_keys[0][i];
            float sc = __uint_as_float(~k);
            if (!(sc >= 0.5f)) {
                st = 2;
            } else {
                st = 0;
                unsigned id = g_vals[0][i];
                float4 b = *reinterpret_cast<const float4*>(&g_boxes[id*4]);
                cand[0] = b.x; cand[1] = b.y; cand[2] = b.z; cand[3] = b.w;
                cand[4] = sc;
            }
        }
        __syncthreads();
        if (st == 2) break;

        float y1 = cand[0], x1 = cand[1], y2 = cand[2], x2 = cand[3];
        float ca = (y2 - y1) * (x2 - x1);
        int m = nsel;
        for (int s = tid; s < m; s += blockDim.x) {
            float iy = fmaxf(0.f, fminf(y2, sy2[s]) - fmaxf(y1, sy1[s]));
            float ix = fmaxf(0.f, fminf(x2, sx2[s]) - fmaxf(x1, sx1[s]));
            float inter = iy * ix;
            float iou = inter / (sar[s] + ca - inter + 1e-9f);
            if (iou > 0.7f) st = 1;
        }
        __syncthreads();
        if (st == 0 && tid == 0) {
            sy1[m] = y1; sx1[m] = x1; sy2[m] = y2; sx2[m] = x2; sar[m] = ca;
            if (m*4 + 3 < out_size) {
                out[m*4 + 0] = y1; out[m*4 + 1] = x1; out[m*4 + 2] = y2; out[m*4 + 3] = x2;
            }
            if (1200 + m < out_size) out[1200 + m] = cand[4];
            if (1500 + m < out_size) out[1500 + m] = 1.f;
            nsel = m + 1;
        }
        __syncthreads();
        if (nsel >= MAX_OUT) break;
    }
}

// ---------------- launch ----------------
extern "C" void kernel_launch(void* const* d_in, const int* in_sizes, int n_in,
                              void* d_out, int out_size)
{
    const float *features = 0, *w1 = 0, *b1 = 0, *w2 = 0, *b2 = 0;
    const float *wsc = 0, *bsc = 0, *wbx = 0, *bbx = 0;
    for (int i = 0; i < n_in; i++) {
        int sz = in_sizes[i];
        const float* p = (const float*)d_in[i];
        switch (sz) {
            case 16777216: features = p; break;
            case 4718592:  w1 = p; break;
            case 2359296:  w2 = p; break;
            case 18432:    wbx = p; break;
            case 4608:     wsc = p; break;
            case 36:       bbx = p; break;
            case 9:        bsc = p; break;
            case 512:      if (!b1) b1 = p; else b2 = p; break;
            default: break;
        }
    }
    if (!b2) b2 = b1;
    float* out = (float*)d_out;

    feat_split_kernel<<<NPIX*1024/256, 256>>>(features);
    wsplit_kernel<true ><<<288*4, 256>>>(w1);
    wsplit_kernel<false><<<144*4, 256>>>(w2);

    const int conv_smem = 184320;    // 3 buffers x (A 30720 + B 30720)
    cudaFuncSetAttribute(conv_mma_kernel<1024, true >, cudaFuncAttributeMaxDynamicSharedMemorySize, conv_smem);
    cudaFuncSetAttribute(conv_mma_kernel< 512, false>, cudaFuncAttributeMaxDynamicSharedMemorySize, conv_smem);
    conv_mma_kernel<1024, true ><<<dim3(HW, 4), 256, conv_smem>>>(b1);
    conv_mma_kernel< 512, false><<<dim3(HW, 4), 256, conv_smem>>>(b2);

    prep_wt_kernel<<<91, 256>>>(wsc, bsc, wbx, bbx);

    const int heads_smem = (45*512 + 16*512 + 16*45) * (int)sizeof(float);
    cudaFuncSetAttribute(heads_kernel, cudaFuncAttributeMaxDynamicSharedMemorySize, heads_smem);
    heads_kernel<<<NPIX/16, 256, heads_smem>>>();

    int src = 0;
    for (int pass = 0; pass < 4; pass++) {
        int shift = pass * 8;
        int dst = src ^ 1;
        radix_hist_kernel<<<144, 256>>>(src, shift);
        radix_scan_kernel<<<1, 1024>>>();
        radix_scatter_kernel<<<144, 256>>>(src, dst, shift);
        src = dst;
    }

    nms_kernel<<<1, 256>>>(out, out_size);
}

// round 13
// speedup vs baseline: 1.1353x; 1.0787x over previous
#include <cuda_runtime.h>
#include <cuda_bf16.h>
#include <math.h>

#define HW 128
#define NPIX (HW*HW)            // 16384
#define NANCH 9
#define NBOX (NPIX*NANCH)       // 147456 = 144*1024
#define IMG_MAX 2048.0f
#define MAX_OUT 300

// ---------------- scratch (static device memory; no allocation) ----------------
__device__ unsigned short g_fs[3][NPIX*1024];    // relu(features) bf16 3-way split
__device__ unsigned short g_as[3][NPIX*512];     // conv1 output bf16 3-way split
__device__ unsigned g_w1s[3][288*4*2048];        // conv1 weights: [tile][n=128][kpair=16]
__device__ unsigned g_w2s[3][144*4*2048];        // conv2 weights
__device__ float g_x2[NPIX*512];                 // conv2 output fp32
__device__ float g_boxes[NBOX*4];
__device__ unsigned g_keys[2][NBOX];
__device__ unsigned g_vals[2][NBOX];
__device__ unsigned g_hist[256*144];
__device__ float g_wt[45*512 + 45];

// ---------------- PTX helpers (compute_103-safe: sm_80 baseline features) ----------------
__device__ __forceinline__ unsigned smem_u32(const void* p) {
    unsigned a;
    asm("{ .reg .u64 t; cvta.to.shared.u64 t, %1; cvt.u32.u64 %0, t; }" : "=r"(a) : "l"(p));
    return a;
}
#define CP16(dst, src) asm volatile("cp.async.cg.shared.global [%0], [%1], 16;" :: "r"(dst), "l"(src) : "memory")
#define CP_COMMIT()    asm volatile("cp.async.commit_group;" ::: "memory")
#define CP_WAIT0()     asm volatile("cp.async.wait_group 0;" ::: "memory")
#define LDSM4(r, addr) asm volatile("ldmatrix.sync.aligned.m8n8.x4.shared.b16 {%0,%1,%2,%3}, [%4];" \
    : "=r"((r)[0]), "=r"((r)[1]), "=r"((r)[2]), "=r"((r)[3]) : "r"(addr))
#define LDSM2(r, addr) asm volatile("ldmatrix.sync.aligned.m8n8.x2.shared.b16 {%0,%1}, [%2];" \
    : "=r"((r)[0]), "=r"((r)[1]) : "r"(addr))
// accumulate variant: D += A*B (tensor-core internal RZ accumulate — keep chains SHORT)
#define MMA16816(dd, aa, bb) \
    asm volatile("mma.sync.aligned.m16n8k16.row.col.f32.bf16.bf16.f32 " \
        "{%0,%1,%2,%3}, {%4,%5,%6,%7}, {%8,%9}, {%0,%1,%2,%3};" \
        : "+f"((dd)[0]), "+f"((dd)[1]), "+f"((dd)[2]), "+f"((dd)[3]) \
        : "r"((aa)[0]), "r"((aa)[1]), "r"((aa)[2]), "r"((aa)[3]), "r"((bb)[0]), "r"((bb)[1]))
// zero-C variant: D = A*B (starts a fresh short chain)
#define MMA16816_Z(dd, aa, bb) \
    asm volatile("mma.sync.aligned.m16n8k16.row.col.f32.bf16.bf16.f32 " \
        "{%0,%1,%2,%3}, {%4,%5,%6,%7}, {%8,%9}, {%10,%11,%12,%13};" \
        : "=f"((dd)[0]), "=f"((dd)[1]), "=f"((dd)[2]), "=f"((dd)[3]) \
        : "r"((aa)[0]), "r"((aa)[1]), "r"((aa)[2]), "r"((aa)[3]), "r"((bb)[0]), "r"((bb)[1]), \
          "f"(0.f), "f"(0.f), "f"(0.f), "f"(0.f))

// ---------------- bf16 3-way exact split ----------------
__device__ __forceinline__ void split3(float v, unsigned short& s0, unsigned short& s1, unsigned short& s2)
{
    __nv_bfloat16 a0 = __float2bfloat16(v);
    float r1 = v - __bfloat162float(a0);
    __nv_bfloat16 a1 = __float2bfloat16(r1);
    float r2 = r1 - __bfloat162float(a1);
    __nv_bfloat16 a2 = __float2bfloat16(r2);
    s0 = __bfloat16_as_ushort(a0);
    s1 = __bfloat16_as_ushort(a1);
    s2 = __bfloat16_as_ushort(a2);
}

// ---------------- feature split: relu + 3-way bf16 ----------------
__global__ void feat_split_kernel(const float* __restrict__ f)
{
    int i = blockIdx.x * 256 + threadIdx.x;     // NPIX*1024 total
    float v = fmaxf(f[i], 0.f);
    unsigned short s0, s1, s2;
    split3(v, s0, s1, s2);
    g_fs[0][i] = s0; g_fs[1][i] = s1; g_fs[2][i] = s2;
}

// ---------------- weight split + transpose into MMA-ready tiles ----------------
template<bool FIRST>
__global__ void wsplit_kernel(const float* __restrict__ w)
{
    __shared__ float ws[32][129];
    const int tile = blockIdx.x;
    const int ch = tile >> 2, nt = tile & 3;
    const int tid = threadIdx.x;                // 256

    for (int i = tid; i < 32*128; i += 256) {
        int kk = i >> 7, nn = i & 127;
        ws[kk][nn] = w[(size_t)(ch*32 + kk)*512 + nt*128 + nn];
    }
    __syncthreads();

    for (int g = tid; g < 2048; g += 256) {
        int nn = g >> 4, kp = g & 15;
        unsigned short a0, a1, a2, b0, b1, b2;
        split3(ws[kp*2][nn],     a0, a1, a2);
        split3(ws[kp*2 + 1][nn], b0, b1, b2);
        size_t o = (size_t)tile*2048 + nn*16 + kp;
        unsigned* d0 = FIRST ? g_w1s[0] : g_w2s[0];
        unsigned* d1 = FIRST ? g_w1s[1] : g_w2s[1];
        unsigned* d2 = FIRST ? g_w1s[2] : g_w2s[2];
        d0[o] = (unsigned)a0 | ((unsigned)b0 << 16);
        d1[o] = (unsigned)a1 | ((unsigned)b1 << 16);
        d2[o] = (unsigned)a2 | ((unsigned)b2 << 16);
    }
}

// ---------------- conv 3x3 as bf16x3 warp-MMA implicit GEMM ----------------
// M=64 tile: grid (256, 4), 256 threads (8 warps 2x4; warp tile 32m x 32n).
// Double-buffered smem (92160B) -> 2 CTAs/SM for cross-CTA latency hiding.
// B fragments hoisted per ks. RN-drain every 2 chunks caps RZ chains.
extern __shared__ unsigned char dynsmem[];

template<int CIN, bool FIRST>
__global__ void __launch_bounds__(256, 2) conv_mma_kernel(const float* __restrict__ bias)
{
    constexpr int CPK = CIN/32;
    constexpr int NCH = 9*CPK;                  // even (288 / 144)
    const int mt = blockIdx.x;                  // 0..255
    const int y  = mt >> 1;
    const int x0 = (mt & 1) << 6;               // 0 or 64
    const int nt = blockIdx.y;
    const int n0 = nt << 7;
    const int tid = threadIdx.x;
    const int wid = tid >> 5, lane = tid & 31;
    const int wm = wid >> 2, wn = wid & 3;      // warp grid 2x4: 32m x 32n per warp

    const unsigned sbase = smem_u32(dynsmem);
    // buffer b (0..1): A at b*46080 (3 splits x 5120B), B at b*46080+15360 (3 x 10240B)
#define A_OFF(buf, t) ((unsigned)((buf)*46080u + (t)*5120u))
#define B_OFF(buf, t) ((unsigned)((buf)*46080u + 15360u + (t)*10240u))

    float d[2][4][4];       // per-segment tensor-core accumulators (short RZ chains)
    float acc[2][4][4];     // master RN accumulators
#pragma unroll
    for (int mi = 0; mi < 2; mi++)
#pragma unroll
        for (int nj = 0; nj < 4; nj++)
#pragma unroll
            for (int q = 0; q < 4; q++) { d[mi][nj][q] = 0.f; acc[mi][nj][q] = 0.f; }

#define LOAD_CHUNK(CH, BUF) do { \
        int _ch = (CH), _buf = (BUF); \
        int _khw = _ch / CPK; \
        int _kh = _khw / 3, _kw = _khw % 3; \
        int _yy = y + _kh - 1; \
        int _c0 = (_ch % CPK) * 32; \
        for (int g = tid; g < 1536; g += 256) { \
            int t = g >> 9, rem = g & 511; \
            int nn = rem >> 2, gg = rem & 3; \
            const unsigned* bsrc = (FIRST ? g_w1s[t] : g_w2s[t]) \
                + ((size_t)(_ch*4 + nt)*2048 + nn*16 + gg*4); \
            CP16(sbase + B_OFF(_buf, t) + nn*80 + gg*16, bsrc); \
        } \
        if (_yy >= 0 && _yy < HW) { \
            for (int g = tid; g < 768; g += 256) { \
                int t = g >> 8, rem = g & 255; \
                int row = rem >> 2, gg = rem & 3; \
                int xx = x0 + row + _kw - 1; \
                if (xx >= 0 && xx < HW) { \
                    const unsigned short* asrc = (FIRST ? g_fs[t] : g_as[t]) \
                        + ((size_t)(_yy*HW + xx)*CIN + _c0 + gg*8); \
                    CP16(sbase + A_OFF(_buf, t) + row*80 + gg*16, asrc); \
                } else { \
                    *reinterpret_cast<uint4*>(dynsmem + A_OFF(_buf, t) + row*80 + gg*16) \
                        = make_uint4(0,0,0,0); \
                } \
            } \
        } else { \
            for (int g = tid; g < 768; g += 256) { \
                int t = g >> 8, rem = g & 255; \
                int row = rem >> 2, gg = rem & 3; \
                *reinterpret_cast<uint4*>(dynsmem + A_OFF(_buf, t) + row*80 + gg*16) \
                    = make_uint4(0,0,0,0); \
            } \
        } \
    } while (0)

    LOAD_CHUNK(0, 0);
    CP_COMMIT();

    for (int ch = 0; ch < NCH; ch++) {
        const int buf = ch & 1;
        const bool segstart = ((ch & 1) == 0);   // segment = 2 chunks
        CP_WAIT0();
        __syncthreads();
        if (ch + 1 < NCH) { LOAD_CHUNK(ch+1, buf ^ 1); CP_COMMIT(); }

        // compute this chunk from smem buf
#pragma unroll
        for (int ks = 0; ks < 2; ks++) {
            const unsigned acol = ks*16 + ((lane >> 4) & 1)*8;
            const unsigned arow = wm*32 + (lane & 7) + ((lane >> 3) & 1)*8;
            const unsigned brow = wn*32 + (lane & 7);
            const unsigned bcol = ks*16 + ((lane >> 3) & 1)*8;

            // hoist ALL B fragments for this ks (reused across the 3 A splits)
            unsigned bfr[3][4][2];
#pragma unroll
            for (int tb = 0; tb < 3; tb++)
#pragma unroll
                for (int nj = 0; nj < 4; nj++) {
                    unsigned baddr = sbase + B_OFF(buf, tb) + (brow + nj*8)*80 + bcol*2;
                    LDSM2(bfr[tb][nj], baddr);
                }

#pragma unroll
            for (int ta = 0; ta < 3; ta++) {
                unsigned afr[2][4];
#pragma unroll
                for (int mi = 0; mi < 2; mi++) {
                    unsigned addr = sbase + A_OFF(buf, ta) + (arow + mi*16)*80 + acol*2;
                    LDSM4(afr[mi], addr);
                }
                const int nb = (ta == 0) ? 3 : ((ta == 1) ? 2 : 1);
#pragma unroll
                for (int tb = 0; tb < 3; tb++) {
                    if (tb >= nb) break;
#pragma unroll
                    for (int nj = 0; nj < 4; nj++) {
                        if (ks == 0 && ta == 0 && tb == 0 && segstart) {
#pragma unroll
                            for (int mi = 0; mi < 2; mi++)
                                MMA16816_Z(d[mi][nj], afr[mi], bfr[tb][nj]);
                        } else {
#pragma unroll
                            for (int mi = 0; mi < 2; mi++)
                                MMA16816(d[mi][nj], afr[mi], bfr[tb][nj]);
                        }
                    }
                }
            }
        }
        if (ch & 1) {   // segment end: RN drain into master accumulators
#pragma unroll
            for (int mi = 0; mi < 2; mi++)
#pragma unroll
                for (int nj = 0; nj < 4; nj++)
#pragma unroll
                    for (int q = 0; q < 4; q++) acc[mi][nj][q] += d[mi][nj][q];
        }
    }

    // epilogue
    const int gid = lane >> 2, tg = lane & 3;
#pragma unroll
    for (int mi = 0; mi < 2; mi++) {
#pragma unroll
        for (int half = 0; half < 2; half++) {
            const int px = y*HW + x0 + wm*32 + mi*16 + gid + half*8;
#pragma unroll
            for (int nj = 0; nj < 4; nj++) {
                const int n = n0 + wn*32 + nj*8 + tg*2;
                float v0 = acc[mi][nj][half*2 + 0] + __ldg(&bias[n]);
                float v1 = acc[mi][nj][half*2 + 1] + __ldg(&bias[n+1]);
                if (FIRST) {
                    v0 = fmaxf(v0, 0.f);
                    v1 = fmaxf(v1, 0.f);
                    unsigned short a0,a1,a2,b0,b1,b2;
                    split3(v0, a0, a1, a2);
                    split3(v1, b0, b1, b2);
                    size_t e = (size_t)px*512 + n;
                    *reinterpret_cast<unsigned*>(&g_as[0][e]) = (unsigned)a0 | ((unsigned)b0 << 16);
                    *reinterpret_cast<unsigned*>(&g_as[1][e]) = (unsigned)a1 | ((unsigned)b1 << 16);
                    *reinterpret_cast<unsigned*>(&g_as[2][e]) = (unsigned)a2 | ((unsigned)b2 << 16);
                } else {
                    *reinterpret_cast<float2*>(&g_x2[(size_t)px*512 + n]) = make_float2(v0, v1);
                }
            }
        }
    }
#undef LOAD_CHUNK
#undef A_OFF
#undef B_OFF
}

// ---------------- head weight transpose ----------------
__global__ void prep_wt_kernel(const float* __restrict__ wsc, const float* __restrict__ bsc,
                               const float* __restrict__ wbx, const float* __restrict__ bbx)
{
    int t = blockIdx.x * blockDim.x + threadIdx.x;
    if (t < 45*512) {
        int o = t / 512, c = t % 512;
        g_wt[t] = (o < 9) ? wsc[c*9 + o] : wbx[c*36 + (o-9)];
    }
    if (t < 45) g_wt[45*512 + t] = (t < 9) ? bsc[t] : bbx[t-9];
}

// ---------------- heads (1x1 conv) + sigmoid + decode + keygen ----------------
__global__ void heads_kernel()
{
    float* ws  = reinterpret_cast<float*>(dynsmem);  // 45*512
    float* xsm = ws + 45*512;                        // 16*512
    float* ho  = xsm + 16*512;                       // 16*45

    const int tid  = threadIdx.x;
    const int lane = tid & 31;
    const int wrp  = tid >> 5;
    const int p0   = blockIdx.x * 16;

    for (int i = tid; i < 45*512; i += 256) ws[i] = g_wt[i];
    for (int i = tid; i < 16*512; i += 256) xsm[i] = g_x2[(size_t)p0*512 + i];
    __syncthreads();

#pragma unroll
    for (int pi = 0; pi < 2; pi++) {
        const int px = wrp*2 + pi;
        float xr[16];
#pragma unroll
        for (int i = 0; i < 16; i++) xr[i] = xsm[px*512 + lane + 32*i];
        for (int o = 0; o < 45; o++) {
            const float* wr = ws + o*512;
            float acc = 0.f;
#pragma unroll
            for (int i = 0; i < 16; i++) acc = fmaf(xr[i], wr[lane + 32*i], acc);
#pragma unroll
            for (int off = 16; off > 0; off >>= 1)
                acc += __shfl_xor_sync(0xFFFFFFFFu, acc, off);
            if (lane == 0) ho[px*45 + o] = acc + g_wt[45*512 + o];
        }
    }
    __syncthreads();

    if (tid < 144) {
        int pp = tid / 9, a = tid % 9;
        int pg = p0 + pp;
        const float* h5 = ho + pp*45;
        float logit = h5[a];
        float sc = 1.f / (1.f + expf(-logit));
        float dy = h5[9 + 4*a + 0];
        float dx = h5[9 + 4*a + 1];
        float dh = h5[9 + 4*a + 2];
        float dw = h5[9 + 4*a + 3];
        int yy = pg >> 7, xx = pg & 127;
        float scale = (a < 3) ? 128.f : ((a < 6) ? 256.f : 512.f);
        int rm = a % 3;
        float ratio = (rm == 0) ? 0.5f : ((rm == 1) ? 1.f : 2.f);
        float sr = sqrtf(ratio);
        float ah = scale * sr, aw = scale / sr;
        float acy = (yy + 0.5f) * 16.f, acx = (xx + 0.5f) * 16.f;
        float cy = acy + dy * ah, cx = acx + dx * aw;
        float h = ah * expf(dh), w = aw * expf(dw);
        float y1 = fminf(fmaxf(cy - 0.5f*h, 0.f), IMG_MAX);
        float x1 = fminf(fmaxf(cx - 0.5f*w, 0.f), IMG_MAX);
        float y2 = fminf(fmaxf(cy + 0.5f*h, 0.f), IMG_MAX);
        float x2 = fminf(fmaxf(cx + 0.5f*w, 0.f), IMG_MAX);
        int idx = pg*9 + a;
        *reinterpret_cast<float4*>(&g_boxes[idx*4]) = make_float4(y1, x1, y2, x2);
        g_keys[0][idx] = ~__float_as_uint(sc);
        g_vals[0][idx] = (unsigned)idx;
    }
}

// ---------------- stable LSD radix sort (4 x 8-bit passes) ----------------
__global__ void radix_hist_kernel(int src, int shift)
{
    __shared__ int h[256];
    const int tid = threadIdx.x;
    h[tid] = 0;
    __syncthreads();
    const int base = blockIdx.x * 1024;
#pragma unroll
    for (int j = 0; j < 4; j++) {
        unsigned k = g_keys[src][base + j*256 + tid];
        atomicAdd(&h[(k >> shift) & 255], 1);
    }
    __syncthreads();
    g_hist[tid*144 + blockIdx.x] = (unsigned)h[tid];
}

__global__ void radix_scan_kernel()
{
    __shared__ unsigned s[1024];
    const int t = threadIdx.x;
    const int base = t * 36;
    unsigned loc[36];
    unsigned sum = 0;
#pragma unroll
    for (int i = 0; i < 36; i++) { loc[i] = g_hist[base + i]; sum += loc[i]; }
    s[t] = sum;
    __syncthreads();
    for (int off = 1; off < 1024; off <<= 1) {
        unsigned v = (t >= off) ? s[t - off] : 0u;
        __syncthreads();
        s[t] += v;
        __syncthreads();
    }
    unsigned run = s[t] - sum;
#pragma unroll
    for (int i = 0; i < 36; i++) { unsigned tmp = loc[i]; g_hist[base + i] = run; run += tmp; }
}

__global__ void radix_scatter_kernel(int src, int dst, int shift)
{
    __shared__ unsigned skey[1024];
    __shared__ unsigned sval[1024];
    __shared__ unsigned char sdig[1024];
    __shared__ unsigned short lrank[1024];
    const int tid = threadIdx.x;
    const int base = blockIdx.x * 1024;
#pragma unroll
    for (int j = 0; j < 4; j++) {
        int i = j*256 + tid;
        unsigned k = g_keys[src][base + i];
        skey[i] = k;
        sval[i] = g_vals[src][base + i];
        sdig[i] = (unsigned char)((k >> shift) & 255);
    }
    __syncthreads();
    {
        unsigned char dg = (unsigned char)tid;
        unsigned short cnt = 0;
        for (int i = 0; i < 1024; i++) {
            if (sdig[i] == dg) lrank[i] = cnt++;
        }
    }
    __syncthreads();
#pragma unroll
    for (int j = 0; j < 4; j++) {
        int i = j*256 + tid;
        unsigned pos = g_hist[(unsigned)sdig[i]*144 + blockIdx.x] + lrank[i];
        g_keys[dst][pos] = skey[i];
        g_vals[dst][pos] = sval[i];
    }
}

// ---------------- greedy NMS over sorted candidates ----------------
__global__ void nms_kernel(float* __restrict__ out, int out_size)
{
    __shared__ float sy1[MAX_OUT], sx1[MAX_OUT], sy2[MAX_OUT], sx2[MAX_OUT], sar[MAX_OUT];
    __shared__ int nsel;
    __shared__ int st;
    __shared__ float cand[5];
    const int tid = threadIdx.x;

    for (int i = tid; i < out_size; i += blockDim.x) out[i] = 0.f;
    if (tid == 0) nsel = 0;
    __syncthreads();

    for (int i = 0; i < NBOX; i++) {
        if (tid == 0) {
            unsigned k = g_keys[0][i];
            float sc = __uint_as_float(~k);
            if (!(sc >= 0.5f)) {
                st = 2;
            } else {
                st = 0;
                unsigned id = g_vals[0][i];
                float4 b = *reinterpret_cast<const float4*>(&g_boxes[id*4]);
                cand[0] = b.x; cand[1] = b.y; cand[2] = b.z; cand[3] = b.w;
                cand[4] = sc;
            }
        }
        __syncthreads();
        if (st == 2) break;

        float y1 = cand[0], x1 = cand[1], y2 = cand[2], x2 = cand[3];
        float ca = (y2 - y1) * (x2 - x1);
        int m = nsel;
        for (int s = tid; s < m; s += blockDim.x) {
            float iy = fmaxf(0.f, fminf(y2, sy2[s]) - fmaxf(y1, sy1[s]));
            float ix = fmaxf(0.f, fminf(x2, sx2[s]) - fmaxf(x1, sx1[s]));
            float inter = iy * ix;
            float iou = inter / (sar[s] + ca - inter + 1e-9f);
            if (iou > 0.7f) st = 1;
        }
        __syncthreads();
        if (st == 0 && tid == 0) {
            sy1[m] = y1; sx1[m] = x1; sy2[m] = y2; sx2[m] = x2; sar[m] = ca;
            if (m*4 + 3 < out_size) {
                out[m*4 + 0] = y1; out[m*4 + 1] = x1; out[m*4 + 2] = y2; out[m*4 + 3] = x2;
            }
            if (1200 + m < out_size) out[1200 + m] = cand[4];
            if (1500 + m < out_size) out[1500 + m] = 1.f;
            nsel = m + 1;
        }
        __syncthreads();
        if (nsel >= MAX_OUT) break;
    }
}

// ---------------- launch ----------------
extern "C" void kernel_launch(void* const* d_in, const int* in_sizes, int n_in,
                              void* d_out, int out_size)
{
    const float *features = 0, *w1 = 0, *b1 = 0, *w2 = 0, *b2 = 0;
    const float *wsc = 0, *bsc = 0, *wbx = 0, *bbx = 0;
    for (int i = 0; i < n_in; i++) {
        int sz = in_sizes[i];
        const float* p = (const float*)d_in[i];
        switch (sz) {
            case 16777216: features = p; break;
            case 4718592:  w1 = p; break;
            case 2359296:  w2 = p; break;
            case 18432:    wbx = p; break;
            case 4608:     wsc = p; break;
            case 36:       bbx = p; break;
            case 9:        bsc = p; break;
            case 512:      if (!b1) b1 = p; else b2 = p; break;
            default: break;
        }
    }
    if (!b2) b2 = b1;
    float* out = (float*)d_out;

    feat_split_kernel<<<NPIX*1024/256, 256>>>(features);
    wsplit_kernel<true ><<<288*4, 256>>>(w1);
    wsplit_kernel<false><<<144*4, 256>>>(w2);

    const int conv_smem = 92160;     // 2 buffers x (A 15360 + B 30720)
    cudaFuncSetAttribute(conv_mma_kernel<1024, true >, cudaFuncAttributeMaxDynamicSharedMemorySize, conv_smem);
    cudaFuncSetAttribute(conv_mma_kernel< 512, false>, cudaFuncAttributeMaxDynamicSharedMemorySize, conv_smem);
    conv_mma_kernel<1024, true ><<<dim3(HW*2, 4), 256, conv_smem>>>(b1);
    conv_mma_kernel< 512, false><<<dim3(HW*2, 4), 256, conv_smem>>>(b2);

    prep_wt_kernel<<<91, 256>>>(wsc, bsc, wbx, bbx);

    const int heads_smem = (45*512 + 16*512 + 16*45) * (int)sizeof(float);
    cudaFuncSetAttribute(heads_kernel, cudaFuncAttributeMaxDynamicSharedMemorySize, heads_smem);
    heads_kernel<<<NPIX/16, 256, heads_smem>>>();

    int src = 0;
    for (int pass = 0; pass < 4; pass++) {
        int shift = pass * 8;
        int dst = src ^ 1;
        radix_hist_kernel<<<144, 256>>>(src, shift);
        radix_scan_kernel<<<1, 1024>>>();
        radix_scatter_kernel<<<144, 256>>>(src, dst, shift);
        src = dst;
    }

    nms_kernel<<<1, 256>>>(out, out_size);
}